// round 2
// baseline (speedup 1.0000x reference)
#include <cuda_runtime.h>
#include <cuda_bf16.h>
#include <cstdint>

// CRF forward scan in exp domain, flag-synchronized persistent kernel.
// E = exp(transitions) f32, held in REGISTERS (16 rows x 8 cols per thread).
// Per step: each thread polls one per-CTA flag, loads its 16B of bf16 W,
// does 64 fma.rn.f32x2, CTA-reduces rows, scales by damped lagged normalizer,
// writes 32B + localmax + release-flag. No global barrier, no atomics.

#define T 2048
#define ROWS 16
#define NBLK 128
#define NTHR 256
#define START_IDX 0
#define END_IDX 1

__device__ __align__(16) float g_Ef[(size_t)T * T];   // 16 MB exp(transitions)
__device__ __align__(16) uint4 g_Wv[2][NBLK][2];      // W: 16 bf16 per entry, 2 halves
__device__ float g_Wmax[2][NBLK];
__device__ int g_flag[NBLK];

__device__ __forceinline__ unsigned long long pack2f(float a, float b) {
    unsigned long long r;
    asm("mov.b64 %0, {%1, %2};" : "=l"(r) : "f"(a), "f"(b));
    return r;
}
__device__ __forceinline__ unsigned long long pack2u(unsigned a, unsigned b) {
    unsigned long long r;
    asm("mov.b64 %0, {%1, %2};" : "=l"(r) : "r"(a), "r"(b));
    return r;
}
__device__ __forceinline__ void unpack2f(unsigned long long p, float& a, float& b) {
    asm("mov.b64 {%0, %1}, %2;" : "=f"(a), "=f"(b) : "l"(p));
}
#define FMA2(acc, a, b) \
    asm("fma.rn.f32x2 %0, %1, %2, %0;" : "+l"(acc) : "l"(a), "l"(b))

__global__ void crf_init(const float* __restrict__ trans) {
    size_t idx = (size_t)blockIdx.x * blockDim.x + threadIdx.x;
    size_t stride = (size_t)gridDim.x * blockDim.x;
    for (size_t i = idx; i < (size_t)T * T; i += stride)
        g_Ef[i] = __expf(trans[i]);
    if (idx < NBLK) {
        uint4 z = make_uint4(0u, 0u, 0u, 0u);
        if (idx == 0) z.x = 0x3F80u;        // bf16(1.0) at tag START_IDX=0 (low half)
        g_Wv[0][idx][0] = z;
        g_Wv[0][idx][1] = make_uint4(0u, 0u, 0u, 0u);
        g_Wmax[0][idx] = (idx == 0) ? 1.0f : 0.0f;
        g_flag[idx] = 0;
    }
}

__global__ void __launch_bounds__(NTHR, 1)
crf_main(const float* __restrict__ h, const float* __restrict__ trans,
         float* __restrict__ out, int S) {
    __shared__ __align__(16) float part[ROWS * NTHR];   // 16 KB row partials
    __shared__ __align__(16) float tmp2[ROWS * 16];
    __shared__ float mxs[NBLK];
    __shared__ float mxp[16];
    __shared__ float outf[ROWS];
    __shared__ __align__(16) unsigned short outb[ROWS];
    __shared__ float sR[2];

    const int tid = threadIdx.x;
    const int wid = tid >> 5;
    const int ln = tid & 31;
    const int b = blockIdx.x;
    const int r0 = b * ROWS;
    const int c0 = wid * 256 + ln * 8;   // first of my 8 columns
    const int ec = c0 >> 4;              // W entry holding my columns
    const int half = (c0 >> 3) & 1;      // which uint4 of that entry

    if (tid == 0) { sR[0] = 1.0f; sR[1] = 1.0f; }

    // E block -> registers: rows r0..r0+15, my 8 cols, packed as f32x2
    unsigned long long e64[ROWS][4];
    #pragma unroll
    for (int r = 0; r < ROWS; r++) {
        const float4* ep = (const float4*)(g_Ef + (size_t)(r0 + r) * T + c0);
        float4 a = ep[0], bb = ep[1];
        e64[r][0] = pack2f(a.x, a.y);
        e64[r][1] = pack2f(a.z, a.w);
        e64[r][2] = pack2f(bb.x, bb.y);
        e64[r][3] = pack2f(bb.z, bb.w);
    }
    __syncthreads();

    float L = 0.0f;

    for (int t = 0; t < S; t++) {
        const int cb = t & 1, nb = cb ^ 1;

        float em = 0.0f;
        if (tid < ROWS) em = __ldg(&h[(size_t)t * T + r0 + tid]);

        // ---- poll the flag(s) this thread depends on ----
        if (tid < NBLK) {
            int f1, f2;
            do {
                asm volatile("ld.acquire.gpu.global.b32 %0, [%1];"
                             : "=r"(f1) : "l"(g_flag + ec));
                asm volatile("ld.acquire.gpu.global.b32 %0, [%1];"
                             : "=r"(f2) : "l"(g_flag + tid));
            } while (f1 < t || f2 < t);
            mxs[tid] = __ldcv(&g_Wmax[cb][tid]);
        } else {
            int f1;
            do {
                asm volatile("ld.acquire.gpu.global.b32 %0, [%1];"
                             : "=r"(f1) : "l"(g_flag + ec));
            } while (f1 < t);
        }

        // ---- my 8 W values (bf16 -> f32x2 pairs) ----
        uint4 wv = __ldcv(&g_Wv[cb][ec][half]);
        unsigned long long w64[4];
        w64[0] = pack2u(wv.x << 16, wv.x & 0xffff0000u);
        w64[1] = pack2u(wv.y << 16, wv.y & 0xffff0000u);
        w64[2] = pack2u(wv.z << 16, wv.z & 0xffff0000u);
        w64[3] = pack2u(wv.w << 16, wv.w & 0xffff0000u);

        // ---- dot: 16 rows x 8 cols, E in regs ----
        #pragma unroll
        for (int r = 0; r < ROWS; r++) {
            unsigned long long acc = 0ULL;   // (0.0f, 0.0f)
            FMA2(acc, e64[r][0], w64[0]);
            FMA2(acc, e64[r][1], w64[1]);
            FMA2(acc, e64[r][2], w64[2]);
            FMA2(acc, e64[r][3], w64[3]);
            float x, y;
            unpack2f(acc, x, y);
            part[r * NTHR + tid] = x + y;
        }
        __syncthreads();   // #1

        // ---- stage1: 256 partials per row -> 16 per row ----
        {
            int rj = tid >> 4, cj = tid & 15;
            const float4* p4 = (const float4*)(part + rj * NTHR + cj * 16);
            float4 a = p4[0], b4 = p4[1], c4 = p4[2], d4 = p4[3];
            tmp2[rj * 16 + cj] =
                ((a.x + a.y) + (a.z + a.w)) + ((b4.x + b4.y) + (b4.z + b4.w)) +
                ((c4.x + c4.y) + (c4.z + c4.w)) + ((d4.x + d4.y) + (d4.z + d4.w));
        }
        if (tid >= 224 && tid < 240) {   // 128 local maxes -> 16
            int j = tid - 224;
            float m = mxs[j * 8];
            #pragma unroll
            for (int k = 1; k < 8; k++) m = fmaxf(m, mxs[j * 8 + k]);
            mxp[j] = m;
        }
        __syncthreads();   // #2

        // ---- stage2: finish rows, scale, emit; compute next normalizer ----
        if (tid < ROWS) {
            const float4* q4 = (const float4*)(tmp2 + tid * 16);
            float4 a = q4[0], b4 = q4[1], c4 = q4[2], d4 = q4[3];
            float rs =
                ((a.x + a.y) + (a.z + a.w)) + ((b4.x + b4.y) + (b4.z + b4.w)) +
                ((c4.x + c4.y) + (c4.z + c4.w)) + ((d4.x + d4.y) + (d4.z + d4.w));
            float rprev = sR[cb];                 // r_{t-1}, computed last step
            float ru_log = 0.25f * __logf(rprev); // damped lagged normalizer
            float rinv = __expf(-ru_log);
            float n = rs * rinv * __expf(em);
            outf[tid] = n;
            outb[tid] = __bfloat16_as_ushort(__float2bfloat16(n));
            if (tid == 0) L += ru_log;
        } else if (tid == 16) {
            float m = mxp[0];
            #pragma unroll
            for (int k = 1; k < 16; k++) m = fmaxf(m, mxp[k]);
            sR[nb] = m;                           // r_t for next step
        }
        __syncthreads();   // #3

        // ---- publish: 32B values + local max + release flag ----
        if (tid == 0) {
            float m = outf[0];
            #pragma unroll
            for (int k = 1; k < ROWS; k++) m = fmaxf(m, outf[k]);
            const uint4* ob = (const uint4*)outb;
            __stcg(&g_Wv[nb][b][0], ob[0]);
            __stcg(&g_Wv[nb][b][1], ob[1]);
            __stcg(&g_Wmax[nb][b], m);
            asm volatile("st.release.gpu.global.b32 [%0], %1;"
                         :: "l"(g_flag + b), "r"(t + 1) : "memory");
        }
    }

    // ---- terminal: logZ = log(sum_j W_S[j]*exp(tr[END,j])) + L ----
    if (b == 0) {
        int f1;
        do {
            asm volatile("ld.acquire.gpu.global.b32 %0, [%1];"
                         : "=r"(f1) : "l"(g_flag + ec));
        } while (f1 < S);
        uint4 wv = __ldcv(&g_Wv[S & 1][ec][half]);
        const float* te = trans + (size_t)END_IDX * T + c0;
        float v0 = __uint_as_float(wv.x << 16), v1 = __uint_as_float(wv.x & 0xffff0000u);
        float v2 = __uint_as_float(wv.y << 16), v3 = __uint_as_float(wv.y & 0xffff0000u);
        float v4 = __uint_as_float(wv.z << 16), v5 = __uint_as_float(wv.z & 0xffff0000u);
        float v6 = __uint_as_float(wv.w << 16), v7 = __uint_as_float(wv.w & 0xffff0000u);
        float p = v0 * __expf(te[0]) + v1 * __expf(te[1]) +
                  v2 * __expf(te[2]) + v3 * __expf(te[3]) +
                  v4 * __expf(te[4]) + v5 * __expf(te[5]) +
                  v6 * __expf(te[6]) + v7 * __expf(te[7]);
        part[tid] = p;
        __syncthreads();
        if (tid == 0) {
            float tot = 0.0f;
            for (int k = 0; k < NTHR; k++) tot += part[k];
            out[0] = __logf(tot) + L;
        }
    }
}

extern "C" void kernel_launch(void* const* d_in, const int* in_sizes, int n_in,
                              void* d_out, int out_size) {
    const float* h = (const float*)d_in[0];
    const float* trans = (const float*)d_in[1];
    float* out = (float*)d_out;
    int S = in_sizes[0] / T;

    crf_init<<<512, 256>>>(trans);
    crf_main<<<NBLK, NTHR>>>(h, trans, out, S);
}

// round 3
// speedup vs baseline: 3.6748x; 3.6748x over previous
#include <cuda_runtime.h>
#include <cuda_bf16.h>
#include <cstdint>

// CRF forward scan in exp domain. Persistent kernel, 128 CTAs.
// E = exp(transitions) f32 in REGISTERS (16 rows x 8 cols per thread, f32x2).
// Sync per step: monotonic global counter, red.release by producer (tid 0),
// polled by exactly ONE thread per CTA. Normalizer = max(W_t), reduced
// concurrently with the dot partials (free — shares the same syncs).

#define T 2048
#define ROWS 16
#define NBLK 128
#define NTHR 256
#define START_IDX 0
#define END_IDX 1

__device__ __align__(16) float g_Ef[(size_t)T * T];   // 16 MB exp(transitions)
__device__ __align__(16) uint4 g_Wv[2][NBLK][2];      // W: 16 bf16 per CTA-entry
__device__ unsigned g_cnt;                            // monotonic step counter

__device__ __forceinline__ unsigned long long pack2f(float a, float b) {
    unsigned long long r;
    asm("mov.b64 %0, {%1, %2};" : "=l"(r) : "f"(a), "f"(b));
    return r;
}
__device__ __forceinline__ unsigned long long pack2u(unsigned a, unsigned b) {
    unsigned long long r;
    asm("mov.b64 %0, {%1, %2};" : "=l"(r) : "r"(a), "r"(b));
    return r;
}
__device__ __forceinline__ void unpack2f(unsigned long long p, float& a, float& b) {
    asm("mov.b64 {%0, %1}, %2;" : "=f"(a), "=f"(b) : "l"(p));
}
#define FMA2(acc, a, b) \
    asm("fma.rn.f32x2 %0, %1, %2, %0;" : "+l"(acc) : "l"(a), "l"(b))

__global__ void crf_init(const float* __restrict__ trans) {
    size_t idx = (size_t)blockIdx.x * blockDim.x + threadIdx.x;
    size_t stride = (size_t)gridDim.x * blockDim.x;
    for (size_t i = idx; i < (size_t)T * T; i += stride)
        g_Ef[i] = __expf(trans[i]);
    if (idx < NBLK) {
        uint4 z = make_uint4(0u, 0u, 0u, 0u);
        if (idx == 0) z.x = 0x3F80u;   // bf16(1.0) at tag START_IDX=0
        g_Wv[0][idx][0] = z;
        g_Wv[0][idx][1] = make_uint4(0u, 0u, 0u, 0u);
    }
    if (idx == 0) g_cnt = 0u;
}

__global__ void __launch_bounds__(NTHR, 1)
crf_main(const float* __restrict__ h, const float* __restrict__ trans,
         float* __restrict__ out, int S) {
    __shared__ __align__(16) float part[ROWS * NTHR];  // 16KB partials
    __shared__ __align__(16) float tmp2[ROWS * 16];
    __shared__ float mxs[NTHR];
    __shared__ float mxp[16];
    __shared__ __align__(16) unsigned short outb[ROWS];

    const int tid = threadIdx.x;
    const int wid = tid >> 5;
    const int ln = tid & 31;
    const int b = blockIdx.x;
    const int r0 = b * ROWS;
    const int c0 = wid * 256 + ln * 8;   // first of my 8 columns
    const int ec = c0 >> 4;              // producer CTA holding my W entry
    const int half = (c0 >> 3) & 1;

    // E block -> registers (f32x2 packed): rows r0..r0+15, my 8 cols
    unsigned long long e64[ROWS][4];
    #pragma unroll
    for (int r = 0; r < ROWS; r++) {
        const float4* ep = (const float4*)(g_Ef + (size_t)(r0 + r) * T + c0);
        float4 a = ep[0], bb = ep[1];
        e64[r][0] = pack2f(a.x, a.y);
        e64[r][1] = pack2f(a.z, a.w);
        e64[r][2] = pack2f(bb.x, bb.y);
        e64[r][3] = pack2f(bb.z, bb.w);
    }

    float L = 0.0f;

    for (int t = 0; t < S; t++) {
        // emissions for my rows (overlaps the poll below)
        float em = 0.0f;
        if (tid < ROWS) em = __ldg(&h[(size_t)t * T + r0 + tid]);

        // ---- wait for all producers of step t (ONE polling thread) ----
        if (tid == 0 && t > 0) {
            const unsigned target = (unsigned)NBLK * (unsigned)t;
            unsigned c;
            do {
                asm volatile("ld.acquire.gpu.global.u32 %0, [%1];"
                             : "=r"(c) : "l"(&g_cnt));
            } while (c < target);
        }
        __syncthreads();

        // ---- my 16B of W (bf16x8) ----
        uint4 wv = __ldcv(&g_Wv[t & 1][ec][half]);
        unsigned long long w64[4];
        w64[0] = pack2u(wv.x << 16, wv.x & 0xffff0000u);
        w64[1] = pack2u(wv.y << 16, wv.y & 0xffff0000u);
        w64[2] = pack2u(wv.z << 16, wv.z & 0xffff0000u);
        w64[3] = pack2u(wv.w << 16, wv.w & 0xffff0000u);

        // thread-local max of my 8 W values (normalizer input)
        {
            float m0 = fmaxf(__uint_as_float(wv.x << 16),
                             __uint_as_float(wv.x & 0xffff0000u));
            float m1 = fmaxf(__uint_as_float(wv.y << 16),
                             __uint_as_float(wv.y & 0xffff0000u));
            float m2 = fmaxf(__uint_as_float(wv.z << 16),
                             __uint_as_float(wv.z & 0xffff0000u));
            float m3 = fmaxf(__uint_as_float(wv.w << 16),
                             __uint_as_float(wv.w & 0xffff0000u));
            mxs[tid] = fmaxf(fmaxf(m0, m1), fmaxf(m2, m3));
        }

        // ---- dot: 16 rows x 8 cols, E in regs ----
        #pragma unroll
        for (int r = 0; r < ROWS; r++) {
            unsigned long long acc = 0ULL;
            FMA2(acc, e64[r][0], w64[0]);
            FMA2(acc, e64[r][1], w64[1]);
            FMA2(acc, e64[r][2], w64[2]);
            FMA2(acc, e64[r][3], w64[3]);
            float x, y;
            unpack2f(acc, x, y);
            part[r * NTHR + tid] = x + y;
        }
        __syncthreads();   // #1

        // ---- stage1: 256 partials/row -> 16/row; 256 maxes -> 16 ----
        {
            int rj = tid >> 4, cj = tid & 15;
            const float4* p4 = (const float4*)(part + rj * NTHR + cj * 16);
            float4 a = p4[0], b4 = p4[1], c4 = p4[2], d4 = p4[3];
            tmp2[rj * 16 + cj] =
                ((a.x + a.y) + (a.z + a.w)) + ((b4.x + b4.y) + (b4.z + b4.w)) +
                ((c4.x + c4.y) + (c4.z + c4.w)) + ((d4.x + d4.y) + (d4.z + d4.w));
        }
        if (tid >= 224 && tid < 240) {
            int j = tid - 224;
            float m = mxs[j * 16];
            #pragma unroll
            for (int k = 1; k < 16; k++) m = fmaxf(m, mxs[j * 16 + k]);
            mxp[j] = m;
        }
        __syncthreads();   // #2

        // ---- stage2 (warp 0, tid<16): finish rows, normalize, emit ----
        if (tid < ROWS) {
            const float4* q4 = (const float4*)(tmp2 + tid * 16);
            float4 a = q4[0], b4 = q4[1], c4 = q4[2], d4 = q4[3];
            float rs =
                ((a.x + a.y) + (a.z + a.w)) + ((b4.x + b4.y) + (b4.z + b4.w)) +
                ((c4.x + c4.y) + (c4.z + c4.w)) + ((d4.x + d4.y) + (d4.z + d4.w));
            // r = max(W_t): identical reduce in every CTA (bit-exact)
            float r = fmaxf(fmaxf(fmaxf(mxp[0], mxp[1]), fmaxf(mxp[2], mxp[3])),
                            fmaxf(fmaxf(mxp[4], mxp[5]), fmaxf(mxp[6], mxp[7])));
            float r2 = fmaxf(fmaxf(fmaxf(mxp[8], mxp[9]), fmaxf(mxp[10], mxp[11])),
                             fmaxf(fmaxf(mxp[12], mxp[13]), fmaxf(mxp[14], mxp[15])));
            r = fmaxf(r, r2);
            float n = rs * (1.0f / r) * __expf(em);
            outb[tid] = __bfloat16_as_ushort(__float2bfloat16(n));
            if (tid == 0) L += __logf(r);
        }
        __syncwarp();
        if (tid == 0) {
            const uint4* ob = (const uint4*)outb;
            __stcg(&g_Wv[(t + 1) & 1][b][0], ob[0]);
            __stcg(&g_Wv[(t + 1) & 1][b][1], ob[1]);
            // release: orders the stores above, lands as one L2 red
            asm volatile("red.release.gpu.global.add.u32 [%0], %1;"
                         :: "l"(&g_cnt), "r"(1u) : "memory");
        }
    }

    // ---- terminal: logZ = log(sum_j W_S[j]*exp(tr[END,j])) + L ----
    if (b == 0) {
        if (tid == 0) {
            const unsigned target = (unsigned)NBLK * (unsigned)S;
            unsigned c;
            do {
                asm volatile("ld.acquire.gpu.global.u32 %0, [%1];"
                             : "=r"(c) : "l"(&g_cnt));
            } while (c < target);
        }
        __syncthreads();
        uint4 wv = __ldcv(&g_Wv[S & 1][ec][half]);
        const float* te = trans + (size_t)END_IDX * T + c0;
        float v0 = __uint_as_float(wv.x << 16), v1 = __uint_as_float(wv.x & 0xffff0000u);
        float v2 = __uint_as_float(wv.y << 16), v3 = __uint_as_float(wv.y & 0xffff0000u);
        float v4 = __uint_as_float(wv.z << 16), v5 = __uint_as_float(wv.z & 0xffff0000u);
        float v6 = __uint_as_float(wv.w << 16), v7 = __uint_as_float(wv.w & 0xffff0000u);
        float p = v0 * __expf(te[0]) + v1 * __expf(te[1]) +
                  v2 * __expf(te[2]) + v3 * __expf(te[3]) +
                  v4 * __expf(te[4]) + v5 * __expf(te[5]) +
                  v6 * __expf(te[6]) + v7 * __expf(te[7]);
        part[tid] = p;
        __syncthreads();
        if (tid == 0) {
            float tot = 0.0f;
            for (int k = 0; k < NTHR; k++) tot += part[k];
            out[0] = __logf(tot) + L;
        }
    }
}

extern "C" void kernel_launch(void* const* d_in, const int* in_sizes, int n_in,
                              void* d_out, int out_size) {
    const float* h = (const float*)d_in[0];
    const float* trans = (const float*)d_in[1];
    float* out = (float*)d_out;
    int S = in_sizes[0] / T;

    crf_init<<<512, 256>>>(trans);
    crf_main<<<NBLK, NTHR>>>(h, trans, out, S);
}